// round 16
// baseline (speedup 1.0000x reference)
#include <cuda_runtime.h>
#include <cuda_fp16.h>
#include <cstdint>

// Problem constants: B=4, H=64, W=2650, C=64, N=680000
#define PB 4
#define PH 64
#define PW 2650
#define PC 64
#define PHW (PH * PW)          // 169600
#define THR 0.5f

// Scratch for BCHW -> BHWC transposed features, fp16 (~87 MB; fg rows ~44 MB).
__device__ __half g_featsT[(size_t)PB * PHW * PC];

// ---------------------------------------------------------------------------
// Kernel 1: mask-aware transpose [B, C, HW] f32 -> [B, HW, C] f16
// R6/R14 configuration + PDL trigger at block end.
// ---------------------------------------------------------------------------
__global__ __launch_bounds__(256) void transpose_bchw_bhwc(
    const float* __restrict__ rf,
    const float* __restrict__ seg)
{
    __shared__ float s[64 * 65];
    __shared__ float sseg[64];

    const int b      = blockIdx.y;
    const int hwBase = blockIdx.x * 64;
    const int t      = threadIdx.x;

    if (t < 64)
        sseg[t] = __ldg(&seg[(size_t)b * PHW + hwBase + t]);

    const float* src = rf + (size_t)b * PC * PHW + hwBase;

    const int cRow = t >> 4;              // 0..15
    const int f4   = t & 15;              // 0..15
#pragma unroll
    for (int pass = 0; pass < 4; pass++) {
        const int c = cRow + pass * 16;
        const float4 v = __ldcs((const float4*)(src + (size_t)c * PHW) + f4);
        s[(f4 * 4 + 0) * 65 + c] = v.x;
        s[(f4 * 4 + 1) * 65 + c] = v.y;
        s[(f4 * 4 + 2) * 65 + c] = v.z;
        s[(f4 * 4 + 3) * 65 + c] = v.w;
    }
    __syncthreads();

    const int q = t & 7;                  // 0..7
#pragma unroll
    for (int pass = 0; pass < 2; pass++) {
        const int row = (t >> 3) + pass * 32;   // 0..63
        if (sseg[row] >= THR) {
            const float* sr = s + row * 65 + q * 8;
            half2 h0 = __floats2half2_rn(sr[0], sr[1]);
            half2 h1 = __floats2half2_rn(sr[2], sr[3]);
            half2 h2 = __floats2half2_rn(sr[4], sr[5]);
            half2 h3 = __floats2half2_rn(sr[6], sr[7]);
            uint4 pack;
            pack.x = *(const unsigned*)&h0;
            pack.y = *(const unsigned*)&h1;
            pack.z = *(const unsigned*)&h2;
            pack.w = *(const unsigned*)&h3;
            uint4* dst = (uint4*)(g_featsT + ((size_t)b * PHW + hwBase + row) * PC);
            dst[q] = pack;
        }
    }

    // PDL: allow the dependent gather grid to launch; prior stores are made
    // visible to it by the trigger's implicit fence.
#if __CUDA_ARCH__ >= 900
    cudaTriggerProgrammaticLaunchCompletion();
#endif
}

// ---------------------------------------------------------------------------
// Kernel 2: R15 gather, restructured for PDL: the scratch-independent index
// chain runs BEFORE cudaGridDependencySynchronize(); scratch reads after.
// ---------------------------------------------------------------------------
__global__ __launch_bounds__(256) void point_gather(
    const float* __restrict__ points,
    const int*   __restrict__ ri,
    const float* __restrict__ seg,
    float*       __restrict__ out,
    float*       __restrict__ mask_out,
    int n)
{
    const int tid   = threadIdx.x;
    const int warp  = tid >> 5;
    const int lane  = tid & 31;
    const int pBase = blockIdx.x * 64 + warp * 8;

    // --- index chain (inputs only — overlaps the transpose tail under PDL) ---
    int   flat_i = 0;
    float m8     = 0.f;
    float pcol   = 0.f;
    if (lane < 8) {
        const int p = pBase + lane;
        if (p < n) {
            const int b = (int)__ldg(&points[(size_t)p * 5]);
            const int2 rc = __ldg((const int2*)(ri + p * 2));
            flat_i = b * PHW + rc.x * PW + rc.y;
            m8 = (__ldg(&seg[flat_i]) >= THR) ? 1.0f : 0.0f;
        }
    }
    // prefetch point columns for the fused column write (also input-only)
    {
        const int k = lane >> 2;              // 0..7
        const int j = lane & 3;               // 0..3 (col 4 handled below)
        const int p = pBase + k;
        if (p < n) pcol = __ldg(&points[(size_t)p * 5 + j]);
    }

    // --- wait for the transpose grid's scratch stores ---
#if __CUDA_ARCH__ >= 900
    cudaGridDependencySynchronize();
#endif

    // --- 8 independent half2 feature gathers (MLP=8 per lane) ---
    half2 v[8];
    float ms[8];
#pragma unroll
    for (int k = 0; k < 8; k++) {
        const int fl = __shfl_sync(0xffffffffu, flat_i, k);
        ms[k]        = __shfl_sync(0xffffffffu, m8,     k);
        v[k] = __floats2half2_rn(0.f, 0.f);
        if (ms[k] != 0.f)
            v[k] = __ldg((const half2*)(g_featsT + (size_t)fl * PC) + lane);
    }

    // --- per-point writeback: features + point columns (R15 shape) ---
#pragma unroll
    for (int k = 0; k < 8; k++) {
        const int p = pBase + k;
        if (p < n) {
            float* row = out + (size_t)p * 69;
            const float2 f = __half22float2(v[k]);
            if (p & 1) {
                __stcs((float2*)(row + 5 + 2 * lane), f);     // STG.64
            } else {
                __stcs(&row[5 + 2 * lane + 0], f.x);
                __stcs(&row[5 + 2 * lane + 1], f.y);
            }
            // point columns 0..3 from prefetch (lanes 4k..4k+3), col 4 below
            if ((lane >> 2) == k)
                __stcs(&row[lane & 3],
                       __shfl_sync(0xffffffffu, pcol, lane) * ms[k]);
            if (lane == 0)
                __stcs(&row[4], __ldg(&points[(size_t)p * 5 + 4]) * ms[k]);
        }
    }

    // --- mask output: lanes 0..7, coalesced ---
    if (lane < 8 && mask_out != nullptr && (pBase + lane) < n)
        __stcs(&mask_out[pBase + lane], m8);
}

// ---------------------------------------------------------------------------
// Launch: transpose, then gather with ProgrammaticStreamSerialization (PDL).
// Falls back to a plain launch if cudaLaunchKernelEx is refused.
// ---------------------------------------------------------------------------
extern "C" void kernel_launch(void* const* d_in, const int* in_sizes, int n_in,
                              void* d_out, int out_size)
{
    const float* points = (const float*)d_in[0];
    const int*   ri     = (const int*)  d_in[1];
    const float* seg    = (const float*)d_in[2];
    const float* rf     = (const float*)d_in[3];

    float* out = (float*)d_out;
    const int n = in_sizes[0] / 5;   // N = 680000

    float* mask_out = nullptr;
    if ((long long)out_size >= (long long)n * 70)
        mask_out = out + (size_t)n * 69;

    // Kernel 1: mask-aware transpose
    {
        dim3 grid(PHW / 64, PB, 1);   // (2650, 4)
        transpose_bchw_bhwc<<<grid, 256>>>(rf, seg);
    }

    // Kernel 2: gather, PDL-launched so its prologue overlaps the transpose tail
    {
        const int blocks = (n + 63) / 64;   // 10625

        cudaLaunchConfig_t cfg = {};
        cfg.gridDim  = dim3((unsigned)blocks, 1, 1);
        cfg.blockDim = dim3(256, 1, 1);
        cfg.dynamicSmemBytes = 0;
        cfg.stream = (cudaStream_t)0;

        cudaLaunchAttribute attr[1];
        attr[0].id = cudaLaunchAttributeProgrammaticStreamSerialization;
        attr[0].val.programmaticStreamSerializationAllowed = 1;
        cfg.attrs = attr;
        cfg.numAttrs = 1;

        cudaError_t err = cudaLaunchKernelEx(&cfg, point_gather,
                                             points, ri, seg, out, mask_out, n);
        if (err != cudaSuccess) {
            // Fallback: plain serialized launch (gridDependencySynchronize
            // is a no-op when not PDL-launched).
            point_gather<<<blocks, 256>>>(points, ri, seg, out, mask_out, n);
        }
    }
}

// round 17
// speedup vs baseline: 4.0537x; 4.0537x over previous
#include <cuda_runtime.h>
#include <cuda_fp16.h>
#include <cstdint>

// Problem constants: B=4, H=64, W=2650, C=64, N=680000
#define PB 4
#define PH 64
#define PW 2650
#define PC 64
#define PHW (PH * PW)          // 169600
#define THR 0.5f

// Scratch for BCHW -> BHWC transposed features, fp16 (~87 MB; fg rows ~44 MB).
__device__ __half g_featsT[(size_t)PB * PHW * PC];

// ---------------------------------------------------------------------------
// Kernel 1: mask-aware transpose [B, C, HW] f32 -> [B, HW, C] f16
// R6/R14/R15 configuration (measured 32.8-35.2 us): 64x64 tile, 256 threads,
// __ldcs float4 streaming loads, fg-gated uint4 packed-half stores.
// ---------------------------------------------------------------------------
__global__ __launch_bounds__(256) void transpose_bchw_bhwc(
    const float* __restrict__ rf,
    const float* __restrict__ seg)
{
    __shared__ float s[64 * 65];
    __shared__ float sseg[64];

    const int b      = blockIdx.y;
    const int hwBase = blockIdx.x * 64;
    const int t      = threadIdx.x;

    if (t < 64)
        sseg[t] = __ldg(&seg[(size_t)b * PHW + hwBase + t]);

    const float* src = rf + (size_t)b * PC * PHW + hwBase;

    const int cRow = t >> 4;              // 0..15
    const int f4   = t & 15;              // 0..15
#pragma unroll
    for (int pass = 0; pass < 4; pass++) {
        const int c = cRow + pass * 16;
        const float4 v = __ldcs((const float4*)(src + (size_t)c * PHW) + f4);
        s[(f4 * 4 + 0) * 65 + c] = v.x;
        s[(f4 * 4 + 1) * 65 + c] = v.y;
        s[(f4 * 4 + 2) * 65 + c] = v.z;
        s[(f4 * 4 + 3) * 65 + c] = v.w;
    }
    __syncthreads();

    const int q = t & 7;                  // 0..7
#pragma unroll
    for (int pass = 0; pass < 2; pass++) {
        const int row = (t >> 3) + pass * 32;   // 0..63
        if (sseg[row] >= THR) {
            const float* sr = s + row * 65 + q * 8;
            half2 h0 = __floats2half2_rn(sr[0], sr[1]);
            half2 h1 = __floats2half2_rn(sr[2], sr[3]);
            half2 h2 = __floats2half2_rn(sr[4], sr[5]);
            half2 h3 = __floats2half2_rn(sr[6], sr[7]);
            uint4 pack;
            pack.x = *(const unsigned*)&h0;
            pack.y = *(const unsigned*)&h1;
            pack.z = *(const unsigned*)&h2;
            pack.w = *(const unsigned*)&h3;
            uint4* dst = (uint4*)(g_featsT + ((size_t)b * PHW + hwBase + row) * PC);
            dst[q] = pack;
        }
    }
}

// ---------------------------------------------------------------------------
// Kernel 2: R15 gather (champion, measured 45.8 us / 78.6 total):
// 8 points per warp, int2 ri load, half2 feature gathers (MLP=8),
// odd-row STG.64 feature stores, fused per-point column writes.
// ---------------------------------------------------------------------------
__global__ __launch_bounds__(256) void point_gather(
    const float* __restrict__ points,
    const int*   __restrict__ ri,
    const float* __restrict__ seg,
    float*       __restrict__ out,
    float*       __restrict__ mask_out,
    int n)
{
    const int tid   = threadIdx.x;
    const int warp  = tid >> 5;
    const int lane  = tid & 31;
    const int pBase = blockIdx.x * 64 + warp * 8;

    // --- index chain for 8 points on lanes 0..7 ---
    int   flat_i = 0;
    float m8     = 0.f;
    if (lane < 8) {
        const int p = pBase + lane;
        if (p < n) {
            const int b = (int)__ldg(&points[(size_t)p * 5]);
            const int2 rc = __ldg((const int2*)(ri + p * 2));
            flat_i = b * PHW + rc.x * PW + rc.y;
            m8 = (__ldg(&seg[flat_i]) >= THR) ? 1.0f : 0.0f;
        }
    }

    // --- 8 independent half2 feature gathers (MLP=8 per lane) ---
    half2 v[8];
    float ms[8];
#pragma unroll
    for (int k = 0; k < 8; k++) {
        const int fl = __shfl_sync(0xffffffffu, flat_i, k);
        ms[k]        = __shfl_sync(0xffffffffu, m8,     k);
        v[k] = __floats2half2_rn(0.f, 0.f);
        if (ms[k] != 0.f)
            v[k] = __ldg((const half2*)(g_featsT + (size_t)fl * PC) + lane);
    }

    // --- per-point writeback: features + point columns in one pass ---
    // pBase is even, so parity of p alternates with k: odd p -> 8B-aligned.
#pragma unroll
    for (int k = 0; k < 8; k++) {
        const int p = pBase + k;
        if (p < n) {
            float* row = out + (size_t)p * 69;
            const float2 f = __half22float2(v[k]);
            if (p & 1) {
                __stcs((float2*)(row + 5 + 2 * lane), f);     // STG.64
            } else {
                __stcs(&row[5 + 2 * lane + 0], f.x);
                __stcs(&row[5 + 2 * lane + 1], f.y);
            }
            // point columns 0..4: lanes 0..4, single 20B line
            if (lane < 5)
                __stcs(&row[lane],
                       __ldg(&points[(size_t)p * 5 + lane]) * ms[k]);
        }
    }

    // --- mask output: lanes 0..7, coalesced ---
    if (lane < 8 && mask_out != nullptr && (pBase + lane) < n)
        __stcs(&mask_out[pBase + lane], m8);
}

// ---------------------------------------------------------------------------
// Launch (serial, default stream — all overlap schemes disproven R13/R16)
// Inputs: points [N,5] f32, ri_indices [N,2] i32,
//         seg_pred [B,H,W] f32, range_features [B,C,H,W] f32
// Output: flattened (out [N,69], mask [N]) as float32.
// ---------------------------------------------------------------------------
extern "C" void kernel_launch(void* const* d_in, const int* in_sizes, int n_in,
                              void* d_out, int out_size)
{
    const float* points = (const float*)d_in[0];
    const int*   ri     = (const int*)  d_in[1];
    const float* seg    = (const float*)d_in[2];
    const float* rf     = (const float*)d_in[3];

    float* out = (float*)d_out;
    const int n = in_sizes[0] / 5;   // N = 680000

    float* mask_out = nullptr;
    if ((long long)out_size >= (long long)n * 70)
        mask_out = out + (size_t)n * 69;

    // Kernel 1: mask-aware transpose (champion config)
    {
        dim3 grid(PHW / 64, PB, 1);   // (2650, 4)
        transpose_bchw_bhwc<<<grid, 256>>>(rf, seg);
    }

    // Kernel 2: gather (champion config)
    {
        const int blocks = (n + 63) / 64;   // 10625
        point_gather<<<blocks, 256>>>(points, ri, seg, out, mask_out, n);
    }
}